// round 7
// baseline (speedup 1.0000x reference)
#include <cuda_runtime.h>
#include <math.h>

#define FULLMASK 0xffffffffu
#define KSEL 9
#define CHUNK 2048

// ---------------- scratch (device globals; no allocation allowed) ----------
__device__ float g_part_focal[4096];   // per-block partial sums of focal_t0
__device__ float g_part_bbox [4096];   // per-(b,g) L1 sums
__device__ float g_part_giou [4096];   // per-(b,g) (1-giou) sums
__device__ float g_part_delta[4096];   // per-(b,g) focal corrections

// ---------------- focal pieces ---------------------------------------------
// focal(x, t=0) = (1-ALPHA) * softplus(x) * sigmoid(x)^2
__device__ __forceinline__ float focal_t0(float x) {
    float ax   = fabsf(x);
    float u    = __expf(-ax);                    // EX2
    float r    = __fdividef(1.0f, 1.0f + u);    // RCP
    float prob = (x >= 0.0f) ? r : (1.0f - r);  // sigmoid(x)
    float sp   = fmaxf(x, 0.0f) + __logf(1.0f + u);  // softplus(x), LG2
    return 0.75f * sp * (prob * prob);
}
// focal(x, t=1) = ALPHA * softplus(-x) * (1-sigmoid(x))^2
__device__ __forceinline__ float focal_t1(float x) {
    float ax   = fabsf(x);
    float u    = __expf(-ax);
    float r    = __fdividef(1.0f, 1.0f + u);
    float prob = (x >= 0.0f) ? r : (1.0f - r);
    float q    = 1.0f - prob;
    float spn  = fmaxf(-x, 0.0f) + __logf(1.0f + u);
    return 0.25f * spn * (q * q);
}

// ---------------- kernel B: streaming focal base sum ------------------------
__global__ void __launch_bounds__(256)
focal_base_kernel(const float* __restrict__ logits, int n4, int total)
{
    const float4* __restrict__ l4 = (const float4*)logits;
    float acc = 0.0f;
    int stride = gridDim.x * blockDim.x;
    for (int i = blockIdx.x * blockDim.x + threadIdx.x; i < n4; i += stride) {
        float4 v = l4[i];
        acc += focal_t0(v.x);
        acc += focal_t0(v.y);
        acc += focal_t0(v.z);
        acc += focal_t0(v.w);
    }
    if (blockIdx.x == 0 && threadIdx.x == 0) {
        for (int i = n4 * 4; i < total; ++i) acc += focal_t0(logits[i]);
    }
    __shared__ float sm[256];
    sm[threadIdx.x] = acc;
    __syncthreads();
#pragma unroll
    for (int s = 128; s > 0; s >>= 1) {
        if (threadIdx.x < s) sm[threadIdx.x] += sm[threadIdx.x + s];
        __syncthreads();
    }
    if (threadIdx.x == 0) g_part_focal[blockIdx.x] = sm[0];
}

// ---------------- kernel A: top-9 selection + box losses + cls corrections --
__global__ void __launch_bounds__(256)
topk_box_kernel(const float*  __restrict__ logits,
                const float4* __restrict__ pred_boxes,   // (B,N,4)
                const float2* __restrict__ locations,    // (N,2)
                const float4* __restrict__ gt_boxes,     // (B,G,4)
                const int*    __restrict__ gt_labels,    // (B,G)
                int B, int N, int C, int G)
{
    __shared__ float2 sloc[CHUNK];
    const int lane = threadIdx.x & 31;
    const int warp = threadIdx.x >> 5;
    const int pair = blockIdx.x * (blockDim.x >> 5) + warp;
    const int P    = B * G;
    const bool active = pair < P;
    const int b = active ? pair / G : 0;
    const int g = active ? pair % G : 0;

    float cx = 0.0f, cy = 0.0f;
    if (active) {
        float4 gb = gt_boxes[b * G + g];
        cx = gb.x; cy = gb.y;
    }

    const float INF = __int_as_float(0x7f800000);
    float dk[KSEL];
    int   ik[KSEL];
#pragma unroll
    for (int j = 0; j < KSEL; ++j) { dk[j] = INF; ik[j] = 0x7fffffff; }

    // scan locations through shared-memory chunks
    for (int base = 0; base < N; base += CHUNK) {
        int cnt = min(CHUNK, N - base);
        __syncthreads();
        for (int i = threadIdx.x; i < cnt; i += blockDim.x)
            sloc[i] = locations[base + i];
        __syncthreads();
        if (active) {
            for (int i = lane; i < cnt; i += 32) {
                float2 L  = sloc[i];
                float dx  = cx - L.x;
                float dy  = cy - L.y;
                float dist = sqrtf(dx * dx + dy * dy);
                if (dist < dk[KSEL - 1]) {
                    dk[KSEL - 1] = dist;
                    ik[KSEL - 1] = base + i;
#pragma unroll
                    for (int j = KSEL - 1; j > 0; --j) {
                        if (dk[j] < dk[j - 1]) {   // strict: stable for ties (new idx larger)
                            float td = dk[j]; dk[j] = dk[j - 1]; dk[j - 1] = td;
                            int   ti = ik[j]; ik[j] = ik[j - 1]; ik[j - 1] = ti;
                        }
                    }
                }
            }
        }
    }

    // merge per-lane top-9 across the warp: 9 rounds of u64 (dist,idx) min
    int myN = 0;
    unsigned long long key =
        (((unsigned long long)__float_as_uint(dk[0])) << 32) | (unsigned)ik[0];
#pragma unroll
    for (int r = 0; r < KSEL; ++r) {
        unsigned long long k = key;
#pragma unroll
        for (int off = 16; off > 0; off >>= 1) {
            unsigned long long o = __shfl_xor_sync(FULLMASK, k, off);
            k = (o < k) ? o : k;
        }
        if (lane == r) myN = (int)(unsigned)(k & 0xffffffffull);
        if (key == k) {   // this lane owned the winner: pop its head
#pragma unroll
            for (int j = 0; j < KSEL - 1; ++j) { dk[j] = dk[j + 1]; ik[j] = ik[j + 1]; }
            dk[KSEL - 1] = INF; ik[KSEL - 1] = 0x7fffffff;
            key = (((unsigned long long)__float_as_uint(dk[0])) << 32) | (unsigned)ik[0];
        }
    }

    // box losses + focal correction for the 9 selected locations
    float l1 = 0.0f, gl = 0.0f, delta = 0.0f;
    if (active && lane < KSEL) {
        float4 pb = pred_boxes[b * N + myN];
        float4 gb = gt_boxes[b * G + g];
        l1 = fabsf(pb.x - gb.x) + fabsf(pb.y - gb.y)
           + fabsf(pb.z - gb.z) + fabsf(pb.w - gb.w);

        // cxcywh -> xyxy
        float ax0 = pb.x - 0.5f * pb.z, ay0 = pb.y - 0.5f * pb.w;
        float ax1 = pb.x + 0.5f * pb.z, ay1 = pb.y + 0.5f * pb.w;
        float bx0 = gb.x - 0.5f * gb.z, by0 = gb.y - 0.5f * gb.w;
        float bx1 = gb.x + 0.5f * gb.z, by1 = gb.y + 0.5f * gb.w;

        float area_a = (ax1 - ax0) * (ay1 - ay0);
        float area_b = (bx1 - bx0) * (by1 - by0);
        float iw = fmaxf(fminf(ax1, bx1) - fmaxf(ax0, bx0), 0.0f);
        float ih = fmaxf(fminf(ay1, by1) - fmaxf(ay0, by0), 0.0f);
        float inter = iw * ih;
        float uni   = area_a + area_b - inter;
        float iou   = inter / uni;
        float cw = fmaxf(fmaxf(ax1, bx1) - fminf(ax0, bx0), 0.0f);
        float ch = fmaxf(fmaxf(ay1, by1) - fminf(ay0, by0), 0.0f);
        float areac = cw * ch;
        float giou  = iou - (areac - uni) / areac;
        gl = 1.0f - giou;

        int lbl = gt_labels[b * G + g];
        float x = logits[(long long)(b * N + myN) * C + lbl];
        delta = focal_t1(x) - focal_t0(x);
    }
#pragma unroll
    for (int off = 16; off > 0; off >>= 1) {
        l1    += __shfl_down_sync(FULLMASK, l1,    off);
        gl    += __shfl_down_sync(FULLMASK, gl,    off);
        delta += __shfl_down_sync(FULLMASK, delta, off);
    }
    if (active && lane == 0) {
        g_part_bbox [pair] = l1;
        g_part_giou [pair] = gl;
        g_part_delta[pair] = delta;
    }
}

// ---------------- kernel C: deterministic final reduction -------------------
__global__ void __launch_bounds__(256)
finalize_kernel(float* __restrict__ out, int nf, int np,
                double invBNC, double invBB, double invGI)
{
    __shared__ double sm[256];
    const int t = threadIdx.x;
    double af = 0.0, ad = 0.0, ab = 0.0, ag = 0.0;
    for (int i = t; i < nf; i += 256) af += (double)g_part_focal[i];
    for (int i = t; i < np; i += 256) {
        ad += (double)g_part_delta[i];
        ab += (double)g_part_bbox [i];
        ag += (double)g_part_giou [i];
    }
    double res0, res1, res2;

    sm[t] = af + ad; __syncthreads();
#pragma unroll
    for (int s = 128; s > 0; s >>= 1) { if (t < s) sm[t] += sm[t + s]; __syncthreads(); }
    res0 = sm[0]; __syncthreads();

    sm[t] = ab; __syncthreads();
#pragma unroll
    for (int s = 128; s > 0; s >>= 1) { if (t < s) sm[t] += sm[t + s]; __syncthreads(); }
    res1 = sm[0]; __syncthreads();

    sm[t] = ag; __syncthreads();
#pragma unroll
    for (int s = 128; s > 0; s >>= 1) { if (t < s) sm[t] += sm[t + s]; __syncthreads(); }
    res2 = sm[0]; __syncthreads();

    if (t == 0) {
        out[0] = (float)(res0 * invBNC);   // loss_cls
        out[1] = (float)(res1 * invBB);    // loss_bbox
        out[2] = (float)(res2 * invGI);    // loss_giou
    }
}

// ---------------- launch ----------------------------------------------------
extern "C" void kernel_launch(void* const* d_in, const int* in_sizes, int n_in,
                              void* d_out, int out_size)
{
    const float* logits = (const float*)d_in[0];   // (B,N,C)
    const float* pboxes = (const float*)d_in[1];   // (B,N,4)
    const float* locs   = (const float*)d_in[2];   // (N,2)
    const float* gboxes = (const float*)d_in[3];   // (B,G,4)
    const int*   glabel = (const int*)  d_in[4];   // (B,G)

    const int N = in_sizes[2] / 2;
    const int B = in_sizes[1] / (4 * N);
    const int C = in_sizes[0] / (B * N);
    const int G = in_sizes[4] / B;
    const int P = B * G;

    const int total = in_sizes[0];
    const int n4    = total / 4;

    // kernel A: one warp per (b,g) pair
    int blocksA = (P + 7) / 8;   // 8 warps per 256-thread block
    topk_box_kernel<<<blocksA, 256>>>(logits, (const float4*)pboxes,
                                      (const float2*)locs, (const float4*)gboxes,
                                      glabel, B, N, C, G);

    // kernel B: streaming focal base
    const int NB = 1184;  // 148 SMs * 8
    focal_base_kernel<<<NB, 256>>>(logits, n4, total);

    // kernel C: finalize
    double invBNC = 1.0 / ((double)B * (double)N * (double)C);
    double invBB  = 1.0 / ((double)P * (double)KSEL * 4.0);
    double invGI  = 1.0 / ((double)P * (double)KSEL);
    finalize_kernel<<<1, 256>>>((float*)d_out, NB, P, invBNC, invBB, invGI);
}

// round 8
// speedup vs baseline: 3.1994x; 3.1994x over previous
#include <cuda_runtime.h>
#include <math.h>

#define FULLMASK 0xffffffffu
#define KSEL    9
#define SEGS    4
#define CHUNK   1792
#define CAP     16
#define GATE2   0.0036f      /* (0.06)^2 — see safety analysis */
#define WARPS_A 8
#define MAXP    4096

// ---------------- scratch (device globals; no allocation allowed) ----------
__device__ unsigned long long g_cand[MAXP * SEGS * KSEL];
__device__ int                g_ovf [MAXP * SEGS];
__device__ float g_part_focal[4096];
__device__ float g_part_bbox [MAXP];
__device__ float g_part_giou [MAXP];
__device__ float g_part_delta[MAXP];

#define INFKEY ((0x7f800000ULL << 32) | 0x7fffffffULL)

// ---------------- focal pieces ---------------------------------------------
__device__ __forceinline__ float focal_t0(float x) {
    float ax   = fabsf(x);
    float u    = __expf(-ax);
    float r    = __fdividef(1.0f, 1.0f + u);
    float prob = (x >= 0.0f) ? r : (1.0f - r);
    float sp   = fmaxf(x, 0.0f) + __logf(1.0f + u);
    return 0.75f * sp * (prob * prob);
}
__device__ __forceinline__ float focal_t1(float x) {
    float ax   = fabsf(x);
    float u    = __expf(-ax);
    float r    = __fdividef(1.0f, 1.0f + u);
    float prob = (x >= 0.0f) ? r : (1.0f - r);
    float q    = 1.0f - prob;
    float spn  = fmaxf(-x, 0.0f) + __logf(1.0f + u);
    return 0.25f * spn * (q * q);
}

// ---------------- top-9 helpers ---------------------------------------------
__device__ __forceinline__ void insert9(float (&dk)[KSEL], int (&ik)[KSEL],
                                        float d, int idx) {
    if (d < dk[KSEL - 1]) {
        dk[KSEL - 1] = d; ik[KSEL - 1] = idx;
#pragma unroll
        for (int j = KSEL - 1; j > 0; --j) {
            if (dk[j] < dk[j - 1]) {
                float td = dk[j]; dk[j] = dk[j - 1]; dk[j - 1] = td;
                int   ti = ik[j]; ik[j] = ik[j - 1]; ik[j - 1] = ti;
            }
        }
    }
}

// warp-merge per-lane sorted lists; lane r (r<9) returns the r-th best key.
__device__ __forceinline__ unsigned long long
warp_merge9(float (&dk)[KSEL], int (&ik)[KSEL], int lane) {
    unsigned long long mykey = INFKEY;
    unsigned long long key =
        (((unsigned long long)__float_as_uint(dk[0])) << 32) | (unsigned)ik[0];
#pragma unroll
    for (int r = 0; r < KSEL; ++r) {
        unsigned long long k = key;
#pragma unroll
        for (int off = 16; off > 0; off >>= 1) {
            unsigned long long o = __shfl_xor_sync(FULLMASK, k, off);
            k = (o < k) ? o : k;
        }
        if (lane == r) mykey = k;
        if (key == k) {
#pragma unroll
            for (int j = 0; j < KSEL - 1; ++j) { dk[j] = dk[j + 1]; ik[j] = ik[j + 1]; }
            dk[KSEL - 1] = __int_as_float(0x7f800000);
            ik[KSEL - 1] = 0x7fffffff;
            key = (((unsigned long long)__float_as_uint(dk[0])) << 32) | (unsigned)ik[0];
        }
    }
    return mykey;
}

// ---------------- kernel A: gated filter + per-(pair,segment) top-9 ---------
__global__ void __launch_bounds__(256)
filter_topk_kernel(const float2* __restrict__ locs,
                   const float4* __restrict__ gt_boxes,
                   int N, int P)
{
    __shared__ __align__(16) float2 sloc[CHUNK];
    __shared__ unsigned long long sstk[WARPS_A][CAP][32];   // [warp][slot][lane]

    const int lane = threadIdx.x & 31;
    const int warp = threadIdx.x >> 5;
    const int seg  = blockIdx.x % SEGS;
    const int pair = (blockIdx.x / SEGS) * WARPS_A + warp;
    const bool active = pair < P;

    float cx = 0.0f, cy = 0.0f;
    if (active) { float4 gb = gt_boxes[pair]; cx = gb.x; cy = gb.y; }

    const int segLen = (N + SEGS - 1) / SEGS;
    const int s0 = seg * segLen;
    const int s1 = min(N, s0 + segLen);

    int cnt = 0;
    for (int base = s0; base < s1; base += CHUNK) {
        int c = min(CHUNK, s1 - base);
        __syncthreads();
        for (int i = threadIdx.x; i < c; i += 256) sloc[i] = locs[base + i];
        __syncthreads();
        if (active) {
            const float4* sl4 = (const float4*)sloc;
            int c2 = c >> 1;
            for (int j = lane; j < c2; j += 32) {
                float4 v  = sl4[j];
                float dx0 = cx - v.x, dy0 = cy - v.y;
                float dx1 = cx - v.z, dy1 = cy - v.w;
                float d0  = fmaf(dx0, dx0, dy0 * dy0);
                float d1  = fmaf(dx1, dx1, dy1 * dy1);
                int   i0  = base + 2 * j;
                if (d0 <= GATE2) {
                    if (cnt < CAP)
                        sstk[warp][cnt][lane] =
                            (((unsigned long long)__float_as_uint(d0)) << 32) | (unsigned)i0;
                    cnt++;
                }
                if (d1 <= GATE2) {
                    if (cnt < CAP)
                        sstk[warp][cnt][lane] =
                            (((unsigned long long)__float_as_uint(d1)) << 32) | (unsigned)(i0 + 1);
                    cnt++;
                }
            }
            if ((c & 1) != 0) {                 // odd tail (not hit for N=21504)
                int i = base + c - 1;
                if (lane == (i & 31)) {
                    float2 L = sloc[c - 1];
                    float dx = cx - L.x, dy = cy - L.y;
                    float d  = fmaf(dx, dx, dy * dy);
                    if (d <= GATE2) {
                        if (cnt < CAP)
                            sstk[warp][cnt][lane] =
                                (((unsigned long long)__float_as_uint(d)) << 32) | (unsigned)i;
                        cnt++;
                    }
                }
            }
        }
    }

    if (!active) return;

    // exact per-lane top-9 over the (tiny) survivor stack
    float dk[KSEL]; int ik[KSEL];
#pragma unroll
    for (int j = 0; j < KSEL; ++j) { dk[j] = __int_as_float(0x7f800000); ik[j] = 0x7fffffff; }
    int m = min(cnt, CAP);
    for (int i = 0; i < CAP; ++i) {
        if (i < m) {
            unsigned long long k = sstk[warp][i][lane];
            insert9(dk, ik, __uint_as_float((unsigned)(k >> 32)), (int)(k & 0xffffffffULL));
        }
    }

    unsigned long long mykey = warp_merge9(dk, ik, lane);
    if (lane < KSEL) g_cand[(pair * SEGS + seg) * KSEL + lane] = mykey;

    int ovf = __ballot_sync(FULLMASK, cnt > CAP);
    if (lane == 0) g_ovf[pair * SEGS + seg] = (ovf != 0);
}

// ---------------- kernel M: final per-pair merge + box losses ---------------
__global__ void __launch_bounds__(256)
merge_box_kernel(const float*  __restrict__ logits,
                 const float4* __restrict__ pred_boxes,
                 const float2* __restrict__ locs,
                 const float4* __restrict__ gt_boxes,
                 const int*    __restrict__ gt_labels,
                 int B, int N, int C, int G)
{
    const int lane = threadIdx.x & 31;
    const int warp = threadIdx.x >> 5;
    const int pair = blockIdx.x * 8 + warp;
    const int P    = B * G;
    if (pair >= P) return;
    const int b = pair / G;

    // load SEGS*KSEL = 36 candidate keys, 2 per lane, sorted pair
    unsigned long long k0 = INFKEY, k1 = INFKEY;
    if (lane      < SEGS * KSEL) k0 = g_cand[pair * SEGS * KSEL + lane];
    if (lane + 32 < SEGS * KSEL) k1 = g_cand[pair * SEGS * KSEL + lane + 32];
    if (k1 < k0) { unsigned long long t = k0; k0 = k1; k1 = t; }

    unsigned long long mykey = INFKEY;
#pragma unroll
    for (int r = 0; r < KSEL; ++r) {
        unsigned long long k = k0;
#pragma unroll
        for (int off = 16; off > 0; off >>= 1) {
            unsigned long long o = __shfl_xor_sync(FULLMASK, k, off);
            k = (o < k) ? o : k;
        }
        if (lane == r) mykey = k;
        if (k0 == k) { k0 = k1; k1 = INFKEY; }
    }

    // safety: gate missed something or a stack overflowed -> exact brute force
    int ovf = 0;
    for (int s = 0; s < SEGS; ++s) ovf |= g_ovf[pair * SEGS + s];
    bool bad = (lane < KSEL) && ((unsigned)(mykey >> 32) >= 0x7f800000u);
    if (ovf || __ballot_sync(FULLMASK, bad)) {
        float dk[KSEL]; int ik[KSEL];
#pragma unroll
        for (int j = 0; j < KSEL; ++j) { dk[j] = __int_as_float(0x7f800000); ik[j] = 0x7fffffff; }
        float4 gb = gt_boxes[pair];
        for (int n = lane; n < N; n += 32) {
            float2 L = locs[n];
            float dx = gb.x - L.x, dy = gb.y - L.y;
            insert9(dk, ik, fmaf(dx, dx, dy * dy), n);
        }
        mykey = warp_merge9(dk, ik, lane);
    }

    // box losses + focal correction for the 9 selected locations
    float l1 = 0.0f, gl = 0.0f, delta = 0.0f;
    if (lane < KSEL) {
        int myN = (int)(mykey & 0xffffffffULL);
        float4 pb = pred_boxes[(long long)b * N + myN];
        float4 gb = gt_boxes[pair];
        l1 = fabsf(pb.x - gb.x) + fabsf(pb.y - gb.y)
           + fabsf(pb.z - gb.z) + fabsf(pb.w - gb.w);

        float ax0 = pb.x - 0.5f * pb.z, ay0 = pb.y - 0.5f * pb.w;
        float ax1 = pb.x + 0.5f * pb.z, ay1 = pb.y + 0.5f * pb.w;
        float bx0 = gb.x - 0.5f * gb.z, by0 = gb.y - 0.5f * gb.w;
        float bx1 = gb.x + 0.5f * gb.z, by1 = gb.y + 0.5f * gb.w;

        float area_a = (ax1 - ax0) * (ay1 - ay0);
        float area_b = (bx1 - bx0) * (by1 - by0);
        float iw = fmaxf(fminf(ax1, bx1) - fmaxf(ax0, bx0), 0.0f);
        float ih = fmaxf(fminf(ay1, by1) - fmaxf(ay0, by0), 0.0f);
        float inter = iw * ih;
        float uni   = area_a + area_b - inter;
        float iou   = inter / uni;
        float cw = fmaxf(fmaxf(ax1, bx1) - fminf(ax0, bx0), 0.0f);
        float ch = fmaxf(fmaxf(ay1, by1) - fminf(ay0, by0), 0.0f);
        float areac = cw * ch;
        gl = 1.0f - (iou - (areac - uni) / areac);

        int lbl = gt_labels[pair];
        float x = logits[(long long)(b * N + myN) * C + lbl];
        delta = focal_t1(x) - focal_t0(x);
    }
#pragma unroll
    for (int off = 16; off > 0; off >>= 1) {
        l1    += __shfl_down_sync(FULLMASK, l1,    off);
        gl    += __shfl_down_sync(FULLMASK, gl,    off);
        delta += __shfl_down_sync(FULLMASK, delta, off);
    }
    if (lane == 0) {
        g_part_bbox [pair] = l1;
        g_part_giou [pair] = gl;
        g_part_delta[pair] = delta;
    }
}

// ---------------- kernel B: streaming focal base sum ------------------------
__global__ void __launch_bounds__(256)
focal_base_kernel(const float* __restrict__ logits, int n4, int total)
{
    const float4* __restrict__ l4 = (const float4*)logits;
    float acc = 0.0f;
    int stride = gridDim.x * blockDim.x;
    for (int i = blockIdx.x * blockDim.x + threadIdx.x; i < n4; i += stride) {
        float4 v = l4[i];
        acc += focal_t0(v.x);
        acc += focal_t0(v.y);
        acc += focal_t0(v.z);
        acc += focal_t0(v.w);
    }
    if (blockIdx.x == 0 && threadIdx.x == 0) {
        for (int i = n4 * 4; i < total; ++i) acc += focal_t0(logits[i]);
    }
    __shared__ float sm[256];
    sm[threadIdx.x] = acc;
    __syncthreads();
#pragma unroll
    for (int s = 128; s > 0; s >>= 1) {
        if (threadIdx.x < s) sm[threadIdx.x] += sm[threadIdx.x + s];
        __syncthreads();
    }
    if (threadIdx.x == 0) g_part_focal[blockIdx.x] = sm[0];
}

// ---------------- kernel C: deterministic final reduction -------------------
__global__ void __launch_bounds__(256)
finalize_kernel(float* __restrict__ out, int nf, int np,
                double invBNC, double invBB, double invGI)
{
    __shared__ double sm[256];
    const int t = threadIdx.x;
    double af = 0.0, ad = 0.0, ab = 0.0, ag = 0.0;
    for (int i = t; i < nf; i += 256) af += (double)g_part_focal[i];
    for (int i = t; i < np; i += 256) {
        ad += (double)g_part_delta[i];
        ab += (double)g_part_bbox [i];
        ag += (double)g_part_giou [i];
    }
    double res0, res1, res2;

    sm[t] = af + ad; __syncthreads();
#pragma unroll
    for (int s = 128; s > 0; s >>= 1) { if (t < s) sm[t] += sm[t + s]; __syncthreads(); }
    res0 = sm[0]; __syncthreads();

    sm[t] = ab; __syncthreads();
#pragma unroll
    for (int s = 128; s > 0; s >>= 1) { if (t < s) sm[t] += sm[t + s]; __syncthreads(); }
    res1 = sm[0]; __syncthreads();

    sm[t] = ag; __syncthreads();
#pragma unroll
    for (int s = 128; s > 0; s >>= 1) { if (t < s) sm[t] += sm[t + s]; __syncthreads(); }
    res2 = sm[0]; __syncthreads();

    if (t == 0) {
        out[0] = (float)(res0 * invBNC);
        out[1] = (float)(res1 * invBB);
        out[2] = (float)(res2 * invGI);
    }
}

// ---------------- launch ----------------------------------------------------
extern "C" void kernel_launch(void* const* d_in, const int* in_sizes, int n_in,
                              void* d_out, int out_size)
{
    const float* logits = (const float*)d_in[0];   // (B,N,C)
    const float* pboxes = (const float*)d_in[1];   // (B,N,4)
    const float* locs   = (const float*)d_in[2];   // (N,2)
    const float* gboxes = (const float*)d_in[3];   // (B,G,4)
    const int*   glabel = (const int*)  d_in[4];   // (B,G)

    const int N = in_sizes[2] / 2;
    const int B = in_sizes[1] / (4 * N);
    const int C = in_sizes[0] / (B * N);
    const int G = in_sizes[4] / B;
    const int P = B * G;

    const int total = in_sizes[0];
    const int n4    = total / 4;

    // A: gated filter + per-(pair,seg) top-9
    int blocksA = ((P + WARPS_A - 1) / WARPS_A) * SEGS;
    filter_topk_kernel<<<blocksA, 256>>>((const float2*)locs,
                                         (const float4*)gboxes, N, P);

    // B: streaming focal base (independent; overlaps A's tail in-graph order)
    const int NB = 1184;
    focal_base_kernel<<<NB, 256>>>(logits, n4, total);

    // M: merge candidates, box losses, focal corrections
    int blocksM = (P + 7) / 8;
    merge_box_kernel<<<blocksM, 256>>>(logits, (const float4*)pboxes,
                                       (const float2*)locs, (const float4*)gboxes,
                                       glabel, B, N, C, G);

    // C: finalize
    double invBNC = 1.0 / ((double)B * (double)N * (double)C);
    double invBB  = 1.0 / ((double)P * (double)KSEL * 4.0);
    double invGI  = 1.0 / ((double)P * (double)KSEL);
    finalize_kernel<<<1, 256>>>((float*)d_out, NB, P, invBNC, invBB, invGI);
}

// round 9
// speedup vs baseline: 3.2028x; 1.0011x over previous
#include <cuda_runtime.h>
#include <math.h>

#define FULLMASK 0xffffffffu
#define KSEL    9
#define SEGS    4
#define CHUNK   1792
#define CAP     16
#define GATE2   0.0036f      /* (0.06)^2 — see safety analysis */
#define WARPS_A 8
#define MAXP    4096

// ---------------- scratch (device globals; no allocation allowed) ----------
__device__ unsigned long long g_cand[MAXP * SEGS * KSEL];
__device__ int                g_ovf [MAXP * SEGS];
__device__ float g_part_focal[4096];
__device__ float g_part_bbox [MAXP];
__device__ float g_part_giou [MAXP];
__device__ float g_part_delta[MAXP];

#define INFKEY ((0x7f800000ULL << 32) | 0x7fffffffULL)

// ---------------- focal pieces ---------------------------------------------
__device__ __forceinline__ float focal_t0(float x) {
    float ax   = fabsf(x);
    float u    = __expf(-ax);
    float r    = __fdividef(1.0f, 1.0f + u);
    float prob = (x >= 0.0f) ? r : (1.0f - r);
    float sp   = fmaxf(x, 0.0f) + __logf(1.0f + u);
    return 0.75f * sp * (prob * prob);
}
__device__ __forceinline__ float focal_t1(float x) {
    float ax   = fabsf(x);
    float u    = __expf(-ax);
    float r    = __fdividef(1.0f, 1.0f + u);
    float prob = (x >= 0.0f) ? r : (1.0f - r);
    float q    = 1.0f - prob;
    float spn  = fmaxf(-x, 0.0f) + __logf(1.0f + u);
    return 0.25f * spn * (q * q);
}

// ---------------- top-9 helpers ---------------------------------------------
__device__ __forceinline__ void insert9(float (&dk)[KSEL], int (&ik)[KSEL],
                                        float d, int idx) {
    if (d < dk[KSEL - 1]) {
        dk[KSEL - 1] = d; ik[KSEL - 1] = idx;
#pragma unroll
        for (int j = KSEL - 1; j > 0; --j) {
            if (dk[j] < dk[j - 1]) {
                float td = dk[j]; dk[j] = dk[j - 1]; dk[j - 1] = td;
                int   ti = ik[j]; ik[j] = ik[j - 1]; ik[j - 1] = ti;
            }
        }
    }
}

// warp-merge per-lane sorted lists; lane r (r<9) returns the r-th best key.
__device__ __forceinline__ unsigned long long
warp_merge9(float (&dk)[KSEL], int (&ik)[KSEL], int lane) {
    unsigned long long mykey = INFKEY;
    unsigned long long key =
        (((unsigned long long)__float_as_uint(dk[0])) << 32) | (unsigned)ik[0];
#pragma unroll
    for (int r = 0; r < KSEL; ++r) {
        unsigned long long k = key;
#pragma unroll
        for (int off = 16; off > 0; off >>= 1) {
            unsigned long long o = __shfl_xor_sync(FULLMASK, k, off);
            k = (o < k) ? o : k;
        }
        if (lane == r) mykey = k;
        if (key == k) {
#pragma unroll
            for (int j = 0; j < KSEL - 1; ++j) { dk[j] = dk[j + 1]; ik[j] = ik[j + 1]; }
            dk[KSEL - 1] = __int_as_float(0x7f800000);
            ik[KSEL - 1] = 0x7fffffff;
            key = (((unsigned long long)__float_as_uint(dk[0])) << 32) | (unsigned)ik[0];
        }
    }
    return mykey;
}

// ---------------- kernel A: gated filter + per-(pair,segment) top-9 ---------
__global__ void __launch_bounds__(256)
filter_topk_kernel(const float2* __restrict__ locs,
                   const float4* __restrict__ gt_boxes,
                   int N, int P)
{
    __shared__ __align__(16) float2 sloc[CHUNK];
    __shared__ unsigned long long sstk[WARPS_A][CAP][32];   // [warp][slot][lane]

    const int lane = threadIdx.x & 31;
    const int warp = threadIdx.x >> 5;
    const int seg  = blockIdx.x % SEGS;
    const int pair = (blockIdx.x / SEGS) * WARPS_A + warp;
    const bool active = pair < P;

    float cx = 0.0f, cy = 0.0f;
    if (active) { float4 gb = gt_boxes[pair]; cx = gb.x; cy = gb.y; }

    const int segLen = (N + SEGS - 1) / SEGS;
    const int s0 = seg * segLen;
    const int s1 = min(N, s0 + segLen);

    int cnt = 0;
    for (int base = s0; base < s1; base += CHUNK) {
        int c = min(CHUNK, s1 - base);
        __syncthreads();
        for (int i = threadIdx.x; i < c; i += 256) sloc[i] = locs[base + i];
        __syncthreads();
        if (active) {
            const float4* sl4 = (const float4*)sloc;
            int c2 = c >> 1;
            for (int j = lane; j < c2; j += 32) {
                float4 v  = sl4[j];
                float dx0 = cx - v.x, dy0 = cy - v.y;
                float dx1 = cx - v.z, dy1 = cy - v.w;
                float d0  = fmaf(dx0, dx0, dy0 * dy0);
                float d1  = fmaf(dx1, dx1, dy1 * dy1);
                int   i0  = base + 2 * j;
                if (d0 <= GATE2) {
                    if (cnt < CAP)
                        sstk[warp][cnt][lane] =
                            (((unsigned long long)__float_as_uint(d0)) << 32) | (unsigned)i0;
                    cnt++;
                }
                if (d1 <= GATE2) {
                    if (cnt < CAP)
                        sstk[warp][cnt][lane] =
                            (((unsigned long long)__float_as_uint(d1)) << 32) | (unsigned)(i0 + 1);
                    cnt++;
                }
            }
            if ((c & 1) != 0) {                 // odd tail (not hit for N=21504)
                int i = base + c - 1;
                if (lane == (i & 31)) {
                    float2 L = sloc[c - 1];
                    float dx = cx - L.x, dy = cy - L.y;
                    float d  = fmaf(dx, dx, dy * dy);
                    if (d <= GATE2) {
                        if (cnt < CAP)
                            sstk[warp][cnt][lane] =
                                (((unsigned long long)__float_as_uint(d)) << 32) | (unsigned)i;
                        cnt++;
                    }
                }
            }
        }
    }

    if (!active) return;

    // exact per-lane top-9 over the (tiny) survivor stack
    float dk[KSEL]; int ik[KSEL];
#pragma unroll
    for (int j = 0; j < KSEL; ++j) { dk[j] = __int_as_float(0x7f800000); ik[j] = 0x7fffffff; }
    int m = min(cnt, CAP);
    for (int i = 0; i < CAP; ++i) {
        if (i < m) {
            unsigned long long k = sstk[warp][i][lane];
            insert9(dk, ik, __uint_as_float((unsigned)(k >> 32)), (int)(k & 0xffffffffULL));
        }
    }

    unsigned long long mykey = warp_merge9(dk, ik, lane);
    if (lane < KSEL) g_cand[(pair * SEGS + seg) * KSEL + lane] = mykey;

    int ovf = __ballot_sync(FULLMASK, cnt > CAP);
    if (lane == 0) g_ovf[pair * SEGS + seg] = (ovf != 0);
}

// ---------------- kernel M: final per-pair merge + box losses ---------------
__global__ void __launch_bounds__(256)
merge_box_kernel(const float*  __restrict__ logits,
                 const float4* __restrict__ pred_boxes,
                 const float2* __restrict__ locs,
                 const float4* __restrict__ gt_boxes,
                 const int*    __restrict__ gt_labels,
                 int B, int N, int C, int G)
{
    const int lane = threadIdx.x & 31;
    const int warp = threadIdx.x >> 5;
    const int pair = blockIdx.x * 8 + warp;
    const int P    = B * G;
    if (pair >= P) return;
    const int b = pair / G;

    // load SEGS*KSEL = 36 candidate keys, 2 per lane, sorted pair
    unsigned long long k0 = INFKEY, k1 = INFKEY;
    if (lane      < SEGS * KSEL) k0 = g_cand[pair * SEGS * KSEL + lane];
    if (lane + 32 < SEGS * KSEL) k1 = g_cand[pair * SEGS * KSEL + lane + 32];
    if (k1 < k0) { unsigned long long t = k0; k0 = k1; k1 = t; }

    unsigned long long mykey = INFKEY;
#pragma unroll
    for (int r = 0; r < KSEL; ++r) {
        unsigned long long k = k0;
#pragma unroll
        for (int off = 16; off > 0; off >>= 1) {
            unsigned long long o = __shfl_xor_sync(FULLMASK, k, off);
            k = (o < k) ? o : k;
        }
        if (lane == r) mykey = k;
        if (k0 == k) { k0 = k1; k1 = INFKEY; }
    }

    // safety: gate missed something or a stack overflowed -> exact brute force
    int ovf = 0;
    for (int s = 0; s < SEGS; ++s) ovf |= g_ovf[pair * SEGS + s];
    bool bad = (lane < KSEL) && ((unsigned)(mykey >> 32) >= 0x7f800000u);
    if (ovf || __ballot_sync(FULLMASK, bad)) {
        float dk[KSEL]; int ik[KSEL];
#pragma unroll
        for (int j = 0; j < KSEL; ++j) { dk[j] = __int_as_float(0x7f800000); ik[j] = 0x7fffffff; }
        float4 gb = gt_boxes[pair];
        for (int n = lane; n < N; n += 32) {
            float2 L = locs[n];
            float dx = gb.x - L.x, dy = gb.y - L.y;
            insert9(dk, ik, fmaf(dx, dx, dy * dy), n);
        }
        mykey = warp_merge9(dk, ik, lane);
    }

    // box losses + focal correction for the 9 selected locations
    float l1 = 0.0f, gl = 0.0f, delta = 0.0f;
    if (lane < KSEL) {
        int myN = (int)(mykey & 0xffffffffULL);
        float4 pb = pred_boxes[(long long)b * N + myN];
        float4 gb = gt_boxes[pair];
        l1 = fabsf(pb.x - gb.x) + fabsf(pb.y - gb.y)
           + fabsf(pb.z - gb.z) + fabsf(pb.w - gb.w);

        float ax0 = pb.x - 0.5f * pb.z, ay0 = pb.y - 0.5f * pb.w;
        float ax1 = pb.x + 0.5f * pb.z, ay1 = pb.y + 0.5f * pb.w;
        float bx0 = gb.x - 0.5f * gb.z, by0 = gb.y - 0.5f * gb.w;
        float bx1 = gb.x + 0.5f * gb.z, by1 = gb.y + 0.5f * gb.w;

        float area_a = (ax1 - ax0) * (ay1 - ay0);
        float area_b = (bx1 - bx0) * (by1 - by0);
        float iw = fmaxf(fminf(ax1, bx1) - fmaxf(ax0, bx0), 0.0f);
        float ih = fmaxf(fminf(ay1, by1) - fmaxf(ay0, by0), 0.0f);
        float inter = iw * ih;
        float uni   = area_a + area_b - inter;
        float iou   = inter / uni;
        float cw = fmaxf(fmaxf(ax1, bx1) - fminf(ax0, bx0), 0.0f);
        float ch = fmaxf(fmaxf(ay1, by1) - fminf(ay0, by0), 0.0f);
        float areac = cw * ch;
        gl = 1.0f - (iou - (areac - uni) / areac);

        int lbl = gt_labels[pair];
        float x = logits[(long long)(b * N + myN) * C + lbl];
        delta = focal_t1(x) - focal_t0(x);
    }
#pragma unroll
    for (int off = 16; off > 0; off >>= 1) {
        l1    += __shfl_down_sync(FULLMASK, l1,    off);
        gl    += __shfl_down_sync(FULLMASK, gl,    off);
        delta += __shfl_down_sync(FULLMASK, delta, off);
    }
    if (lane == 0) {
        g_part_bbox [pair] = l1;
        g_part_giou [pair] = gl;
        g_part_delta[pair] = delta;
    }
}

// ---------------- kernel B: streaming focal base sum ------------------------
__global__ void __launch_bounds__(256)
focal_base_kernel(const float* __restrict__ logits, int n4, int total)
{
    const float4* __restrict__ l4 = (const float4*)logits;
    float acc = 0.0f;
    int stride = gridDim.x * blockDim.x;
    for (int i = blockIdx.x * blockDim.x + threadIdx.x; i < n4; i += stride) {
        float4 v = l4[i];
        acc += focal_t0(v.x);
        acc += focal_t0(v.y);
        acc += focal_t0(v.z);
        acc += focal_t0(v.w);
    }
    if (blockIdx.x == 0 && threadIdx.x == 0) {
        for (int i = n4 * 4; i < total; ++i) acc += focal_t0(logits[i]);
    }
    __shared__ float sm[256];
    sm[threadIdx.x] = acc;
    __syncthreads();
#pragma unroll
    for (int s = 128; s > 0; s >>= 1) {
        if (threadIdx.x < s) sm[threadIdx.x] += sm[threadIdx.x + s];
        __syncthreads();
    }
    if (threadIdx.x == 0) g_part_focal[blockIdx.x] = sm[0];
}

// ---------------- kernel C: deterministic final reduction -------------------
__global__ void __launch_bounds__(256)
finalize_kernel(float* __restrict__ out, int nf, int np,
                double invBNC, double invBB, double invGI)
{
    __shared__ double sm[256];
    const int t = threadIdx.x;
    double af = 0.0, ad = 0.0, ab = 0.0, ag = 0.0;
    for (int i = t; i < nf; i += 256) af += (double)g_part_focal[i];
    for (int i = t; i < np; i += 256) {
        ad += (double)g_part_delta[i];
        ab += (double)g_part_bbox [i];
        ag += (double)g_part_giou [i];
    }
    double res0, res1, res2;

    sm[t] = af + ad; __syncthreads();
#pragma unroll
    for (int s = 128; s > 0; s >>= 1) { if (t < s) sm[t] += sm[t + s]; __syncthreads(); }
    res0 = sm[0]; __syncthreads();

    sm[t] = ab; __syncthreads();
#pragma unroll
    for (int s = 128; s > 0; s >>= 1) { if (t < s) sm[t] += sm[t + s]; __syncthreads(); }
    res1 = sm[0]; __syncthreads();

    sm[t] = ag; __syncthreads();
#pragma unroll
    for (int s = 128; s > 0; s >>= 1) { if (t < s) sm[t] += sm[t + s]; __syncthreads(); }
    res2 = sm[0]; __syncthreads();

    if (t == 0) {
        out[0] = (float)(res0 * invBNC);
        out[1] = (float)(res1 * invBB);
        out[2] = (float)(res2 * invGI);
    }
}

// ---------------- launch ----------------------------------------------------
extern "C" void kernel_launch(void* const* d_in, const int* in_sizes, int n_in,
                              void* d_out, int out_size)
{
    const float* logits = (const float*)d_in[0];   // (B,N,C)
    const float* pboxes = (const float*)d_in[1];   // (B,N,4)
    const float* locs   = (const float*)d_in[2];   // (N,2)
    const float* gboxes = (const float*)d_in[3];   // (B,G,4)
    const int*   glabel = (const int*)  d_in[4];   // (B,G)

    const int N = in_sizes[2] / 2;
    const int B = in_sizes[1] / (4 * N);
    const int C = in_sizes[0] / (B * N);
    const int G = in_sizes[4] / B;
    const int P = B * G;

    const int total = in_sizes[0];
    const int n4    = total / 4;

    // A: gated filter + per-(pair,seg) top-9
    int blocksA = ((P + WARPS_A - 1) / WARPS_A) * SEGS;
    filter_topk_kernel<<<blocksA, 256>>>((const float2*)locs,
                                         (const float4*)gboxes, N, P);

    // B: streaming focal base (independent; overlaps A's tail in-graph order)
    const int NB = 1184;
    focal_base_kernel<<<NB, 256>>>(logits, n4, total);

    // M: merge candidates, box losses, focal corrections
    int blocksM = (P + 7) / 8;
    merge_box_kernel<<<blocksM, 256>>>(logits, (const float4*)pboxes,
                                       (const float2*)locs, (const float4*)gboxes,
                                       glabel, B, N, C, G);

    // C: finalize
    double invBNC = 1.0 / ((double)B * (double)N * (double)C);
    double invBB  = 1.0 / ((double)P * (double)KSEL * 4.0);
    double invGI  = 1.0 / ((double)P * (double)KSEL);
    finalize_kernel<<<1, 256>>>((float*)d_out, NB, P, invBNC, invBB, invGI);
}